// round 7
// baseline (speedup 1.0000x reference)
#include <cuda_runtime.h>

typedef unsigned long long u64;

#define N_POS   16384
#define CDIM    128
#define CTOT    512
#define BATCH   2
#define BH      8
#define SCALE   0.08838834764831845f

// Scratch (allocation-free): per-(b,h) kv matrices + k row-sums.
__device__ float g_kv[BH * CDIM * CDIM];
__device__ float g_ksum[BH * CDIM];

// ---------------- packed f32x2 helpers ----------------
__device__ __forceinline__ u64 pk2(float x, float y) {
    u64 r; asm("mov.b64 %0, {%1, %2};" : "=l"(r) : "f"(x), "f"(y)); return r;
}
__device__ __forceinline__ void fma2(u64 &d, u64 a, u64 b) {
    asm("fma.rn.f32x2 %0, %1, %2, %0;" : "+l"(d) : "l"(a), "l"(b));
}
__device__ __forceinline__ float2 up2(u64 v) {
    float2 f; asm("mov.b64 {%0, %1}, %2;" : "=f"(f.x), "=f"(f.y) : "l"(v)); return f;
}
__device__ __forceinline__ float softplus(float x) {
    // log1p(exp(x)) = max(x,0) + log(1 + exp(-|x|))
    return fmaxf(x, 0.0f) + __logf(1.0f + __expf(-fabsf(x)));
}

// 8x8 rank-1 update in packed f32x2: acc[i][p] += a[i] * (b[2p], b[2p+1])
__device__ __forceinline__ void rank1(u64 (&acc)[8][4],
                                      const float* __restrict__ ar,
                                      const float* __restrict__ br) {
    float4 a0 = *(const float4*)ar;
    float4 a1 = *(const float4*)(ar + 4);
    ulonglong2 b01 = *(const ulonglong2*)br;        // pairs already packed
    ulonglong2 b23 = *(const ulonglong2*)(br + 4);
    u64 bb[4] = { b01.x, b01.y, b23.x, b23.y };
    u64 ad[8];
    ad[0] = pk2(a0.x, a0.x); ad[1] = pk2(a0.y, a0.y);
    ad[2] = pk2(a0.z, a0.z); ad[3] = pk2(a0.w, a0.w);
    ad[4] = pk2(a1.x, a1.x); ad[5] = pk2(a1.y, a1.y);
    ad[6] = pk2(a1.z, a1.z); ad[7] = pk2(a1.w, a1.w);
#pragma unroll
    for (int i = 0; i < 8; i++)
#pragma unroll
        for (int p = 0; p < 4; p++)
            fma2(acc[i][p], ad[i], bb[p]);
}

// ---------------- zero scratch ----------------
__global__ void zero_kernel() {
    int i = blockIdx.x * blockDim.x + threadIdx.x;
    if (i < BH * CDIM * CDIM) g_kv[i]   = 0.0f;
    if (i < BH * CDIM)        g_ksum[i] = 0.0f;
}

// ---------------- pass 1: kv = softplus(K) @ V^T, ksum = softplus(K) @ 1 ----------------
#define P1_CHUNK 256
#define P1_STEPS 16
#define SKS 132   // padded transpose stride

__global__ __launch_bounds__(256, 2) void kv_kernel(const float* __restrict__ x) {
    __shared__ float sk[2][16][SKS];
    __shared__ float sv[2][16][SKS];
    __shared__ float ksum_s[CDIM];

    const int tid = threadIdx.x;
    const int bh  = blockIdx.y;
    const int b   = bh >> 2, h = bh & 3;
    const size_t S    = (size_t)BATCH * CTOT * N_POS;
    const size_t base = (size_t)(b * CTOT + h * CDIM) * N_POS + (size_t)blockIdx.x * P1_CHUNK;
    const float* kp = x + S + base;
    const float* vp = x + 2 * S + base;

    if (tid < CDIM) ksum_s[tid] = 0.0f;

    const int col4 = (tid & 3) * 4;     // n-offset within 16-wide k-step
    const int r0   = tid >> 2;          // rows r0 and r0+64
    const int tr8  = (tid >> 4) * 8;    // output c-tile
    const int tc8  = (tid & 15) * 8;    // output d-tile

    u64 acc[8][4];
#pragma unroll
    for (int i = 0; i < 8; i++)
#pragma unroll
        for (int p = 0; p < 4; p++) acc[i][p] = 0ULL;

    float ks0 = 0.0f, ks1 = 0.0f;

    float4 kr0 = *(const float4*)(kp + (size_t)r0 * N_POS + col4);
    float4 kr1 = *(const float4*)(kp + (size_t)(r0 + 64) * N_POS + col4);
    float4 vr0 = *(const float4*)(vp + (size_t)r0 * N_POS + col4);
    float4 vr1 = *(const float4*)(vp + (size_t)(r0 + 64) * N_POS + col4);

    for (int s = 0; s < P1_STEPS; s++) {
        const int buf = s & 1;
        {
            float t0 = softplus(kr0.x), t1 = softplus(kr0.y),
                  t2 = softplus(kr0.z), t3 = softplus(kr0.w);
            ks0 += (t0 + t1) + (t2 + t3);
            sk[buf][col4 + 0][r0] = t0; sk[buf][col4 + 1][r0] = t1;
            sk[buf][col4 + 2][r0] = t2; sk[buf][col4 + 3][r0] = t3;
            t0 = softplus(kr1.x); t1 = softplus(kr1.y);
            t2 = softplus(kr1.z); t3 = softplus(kr1.w);
            ks1 += (t0 + t1) + (t2 + t3);
            sk[buf][col4 + 0][r0 + 64] = t0; sk[buf][col4 + 1][r0 + 64] = t1;
            sk[buf][col4 + 2][r0 + 64] = t2; sk[buf][col4 + 3][r0 + 64] = t3;
            sv[buf][col4 + 0][r0] = vr0.x; sv[buf][col4 + 1][r0] = vr0.y;
            sv[buf][col4 + 2][r0] = vr0.z; sv[buf][col4 + 3][r0] = vr0.w;
            sv[buf][col4 + 0][r0 + 64] = vr1.x; sv[buf][col4 + 1][r0 + 64] = vr1.y;
            sv[buf][col4 + 2][r0 + 64] = vr1.z; sv[buf][col4 + 3][r0 + 64] = vr1.w;
        }
        __syncthreads();
        if (s + 1 < P1_STEPS) {
            const size_t off = (size_t)(s + 1) * 16 + col4;
            kr0 = *(const float4*)(kp + (size_t)r0 * N_POS + off);
            kr1 = *(const float4*)(kp + (size_t)(r0 + 64) * N_POS + off);
            vr0 = *(const float4*)(vp + (size_t)r0 * N_POS + off);
            vr1 = *(const float4*)(vp + (size_t)(r0 + 64) * N_POS + off);
        }
#pragma unroll
        for (int kk = 0; kk < 16; kk++)
            rank1(acc, &sk[buf][kk][tr8], &sv[buf][kk][tc8]);
    }

    atomicAdd(&ksum_s[r0],      ks0);
    atomicAdd(&ksum_s[r0 + 64], ks1);
    __syncthreads();
    if (tid < CDIM) atomicAdd(&g_ksum[bh * CDIM + tid], ksum_s[tid]);

    float* kvb = g_kv + bh * CDIM * CDIM;
#pragma unroll
    for (int i = 0; i < 8; i++) {
        float* row = kvb + (tr8 + i) * CDIM + tc8;
#pragma unroll
        for (int p = 0; p < 4; p++) {
            float2 v = up2(acc[i][p]);
            atomicAdd(row + 2 * p,     v.x);
            atomicAdd(row + 2 * p + 1, v.y);
        }
    }
}

// ---------------- pass 2: out[d,n] = scale*zinv[n] * sum_c softplus(q)[c,n]*kv[c,d] ----------------
#define P2_SMEM_FLOATS 21760   // skv 16384 + qs 4096 + zred 1024 + zinv 128 + ksum 128

__global__ __launch_bounds__(256, 2) void out_kernel(const float* __restrict__ x,
                                                     float* __restrict__ out) {
    extern __shared__ float sm[];
    float* skv  = sm;            // [128][128]
    float* qs   = sm + 16384;    // [2][16][128]
    float* zred = sm + 20480;    // [8][128]
    float* zinv = sm + 21504;    // [128]
    float* ksm  = sm + 21632;    // [128]

    const int tid = threadIdx.x;
    const int bh  = blockIdx.y;
    const int b   = bh >> 2, h = bh & 3;
    const size_t rowbase = (size_t)(b * CTOT + h * CDIM) * N_POS + (size_t)blockIdx.x * 128;
    const float* qp = x + rowbase;          // q = x[0]
    float* op = out + rowbase;

    {   // cache full kv[bh] (mostly L2 hits: 128 blocks share it)
        const float4* src = (const float4*)(g_kv + bh * CDIM * CDIM);
        float4* dst = (float4*)skv;
#pragma unroll
        for (int i = 0; i < 16; i++) dst[tid + i * 256] = src[tid + i * 256];
    }
    if (tid < CDIM) ksm[tid] = g_ksum[bh * CDIM + tid];

    const int n4   = (tid & 31) * 4;    // fixed n-columns per thread (load/z)
    const int crow = tid >> 5;          // 0..7
    const int tr8  = (tid >> 4) * 8;    // output d-tile
    const int tc8  = (tid & 15) * 8;    // output n-tile

    u64 acc[8][4];
#pragma unroll
    for (int i = 0; i < 8; i++)
#pragma unroll
        for (int p = 0; p < 4; p++) acc[i][p] = 0ULL;
    float z0 = 0.f, z1 = 0.f, z2 = 0.f, z3 = 0.f;

    float4 qr0 = *(const float4*)(qp + (size_t)crow * N_POS + n4);
    float4 qr1 = *(const float4*)(qp + (size_t)(crow + 8) * N_POS + n4);

    __syncthreads();

    for (int s = 0; s < 8; s++) {
        const int buf = s & 1;
        float* qb = qs + buf * 2048;
        {
            float t0 = softplus(qr0.x), t1 = softplus(qr0.y),
                  t2 = softplus(qr0.z), t3 = softplus(qr0.w);
            float kw = ksm[s * 16 + crow];
            z0 += t0 * kw; z1 += t1 * kw; z2 += t2 * kw; z3 += t3 * kw;
            *(float4*)(qb + crow * 128 + n4) = make_float4(t0, t1, t2, t3);
            t0 = softplus(qr1.x); t1 = softplus(qr1.y);
            t2 = softplus(qr1.z); t3 = softplus(qr1.w);
            kw = ksm[s * 16 + crow + 8];
            z0 += t0 * kw; z1 += t1 * kw; z2 += t2 * kw; z3 += t3 * kw;
            *(float4*)(qb + (crow + 8) * 128 + n4) = make_float4(t0, t1, t2, t3);
        }
        __syncthreads();
        if (s < 7) {
            const float* qn = qp + (size_t)(s + 1) * 16 * N_POS;
            qr0 = *(const float4*)(qn + (size_t)crow * N_POS + n4);
            qr1 = *(const float4*)(qn + (size_t)(crow + 8) * N_POS + n4);
        }
#pragma unroll
        for (int kk = 0; kk < 16; kk++)
            rank1(acc, &skv[(s * 16 + kk) * CDIM + tr8], qb + kk * 128 + tc8);
    }

    // z reduction: 8 partials per n column
    *(float4*)(zred + crow * 128 + n4) = make_float4(z0, z1, z2, z3);
    __syncthreads();
    if (tid < 128) {
        float zs = 0.0f;
#pragma unroll
        for (int r = 0; r < 8; r++) zs += zred[r * 128 + tid];
        zinv[tid] = SCALE / (zs * SCALE + (float)N_POS);  // folds out-scale
    }
    __syncthreads();

    float zv[8];
#pragma unroll
    for (int j = 0; j < 8; j++) zv[j] = zinv[tc8 + j];
#pragma unroll
    for (int i = 0; i < 8; i++) {
        float* row = op + (size_t)(tr8 + i) * N_POS + tc8;
        float o[8];
#pragma unroll
        for (int p = 0; p < 4; p++) {
            float2 v = up2(acc[i][p]);
            o[2 * p]     = v.x * zv[2 * p];
            o[2 * p + 1] = v.y * zv[2 * p + 1];
        }
        *(float4*)(row)     = make_float4(o[0], o[1], o[2], o[3]);
        *(float4*)(row + 4) = make_float4(o[4], o[5], o[6], o[7]);
    }
}

// ---------------- launch ----------------
extern "C" void kernel_launch(void* const* d_in, const int* in_sizes, int n_in,
                              void* d_out, int out_size) {
    (void)in_sizes; (void)n_in; (void)out_size;
    const float* x = (const float*)d_in[0];
    float* out = (float*)d_out;

    cudaFuncSetAttribute(out_kernel, cudaFuncAttributeMaxDynamicSharedMemorySize,
                         P2_SMEM_FLOATS * (int)sizeof(float));

    zero_kernel<<<(BH * CDIM * CDIM + 255) / 256, 256>>>();
    kv_kernel<<<dim3(64, BH), 256>>>(x);
    out_kernel<<<dim3(128, BH), 256, P2_SMEM_FLOATS * sizeof(float)>>>(x, out);
}

// round 9
// speedup vs baseline: 1.4809x; 1.4809x over previous
#include <cuda_runtime.h>
#include <cuda_fp16.h>
#include <mma.h>
#include <cstdint>

using namespace nvcuda;
typedef uint32_t u32;

#define N_POS 16384
#define CDIM  128
#define CTOT  512
#define BH    8
#define SCALE 0.08838834764831845f

// Scratch (allocation-free): kv transposed [bh][d][c] and ksum[bh][c]
__device__ float g_kvt[BH * CDIM * CDIM];
__device__ float g_ksum[BH * CDIM];

__device__ __forceinline__ float softplus(float x) {
    return fmaxf(x, 0.0f) + __logf(1.0f + __expf(-fabsf(x)));
}

// Split a float4 into fp16 hi + fp16 lo (exact-ish 2-term decomposition) and
// store 4 contiguous halves to each of hi/lo (8B vector stores).
__device__ __forceinline__ void split_store4(float4 f, __half* hip, __half* lop) {
    __half hx = __float2half_rn(f.x), hy = __float2half_rn(f.y),
           hz = __float2half_rn(f.z), hw = __float2half_rn(f.w);
    float lx = f.x - __half2float(hx), ly = f.y - __half2float(hy),
          lz = f.z - __half2float(hz), lw = f.w - __half2float(hw);
    __half2 h0 = __halves2half2(hx, hy), h1 = __halves2half2(hz, hw);
    *(uint2*)hip = make_uint2(*(u32*)&h0, *(u32*)&h1);
    __half2 l0 = __floats2half2_rn(lx, ly), l1 = __floats2half2_rn(lz, lw);
    *(uint2*)lop = make_uint2(*(u32*)&l0, *(u32*)&l1);
}

__global__ void zero_kernel() {
    int i = blockIdx.x * blockDim.x + threadIdx.x;
    if (i < BH * CDIM * CDIM) g_kvt[i] = 0.0f;
    if (i < BH * CDIM)        g_ksum[i] = 0.0f;
}

// ==================== pass 1 ====================
// kv_t[d][c] += sum_n v[d,n] * softplus(k)[c,n];  ksum[c] += sum_n softplus(k)[c,n]
// grid (16, BH): each CTA owns a 1024-wide n range, 32 chunks of 32.
// smem tiles per buffer: V_hi, V_lo, K_hi, K_lo each [128 rows][40 halves] (rows=d or c, cols=n)
#define LD1    40
#define TILE_H (128 * LD1)          // 5120 halves
#define BUF_H  (4 * TILE_H)         // 20480 halves
#define P1_SMEM (2 * BUF_H * 2)     // 81920 bytes (also reused for 64KB fp32 epilogue)

__global__ void __launch_bounds__(256, 1) pass1_kernel(const float* __restrict__ x) {
    extern __shared__ __align__(16) __half smh[];
    const int tid = threadIdx.x, wid = tid >> 5;
    const int bh = blockIdx.y, b = bh >> 2, h = bh & 3;
    const int isK = tid >> 7;         // threads 0..127: v rows (A); 128..255: k rows (B)
    const int row = tid & 127;
    const size_t S = (size_t)2 * CTOT * N_POS;
    const float* gp = x + (size_t)(isK ? 1 : 2) * S
                    + ((size_t)(b * CTOT + h * CDIM + row)) * N_POS
                    + (size_t)blockIdx.x * 1024;

    float4 pf[8];
#pragma unroll
    for (int j = 0; j < 8; j++) pf[j] = ((const float4*)gp)[j];

    float ksacc = 0.0f;
    const int wm = wid & 3, wn = wid >> 2;   // warp tile: m(d)=32*wm, n(c)=64*wn

    wmma::fragment<wmma::accumulator, 16, 16, 16, float> acc[2][4];
#pragma unroll
    for (int i = 0; i < 2; i++)
#pragma unroll
        for (int j = 0; j < 4; j++) wmma::fill_fragment(acc[i][j], 0.0f);

    for (int s = 0; s < 32; s++) {
        __half* tb = smh + (s & 1) * BUF_H;
        __half* hip = tb + (isK ? 2 * TILE_H : 0) + row * LD1;
        __half* lop = hip + TILE_H;
        if (isK) {
#pragma unroll
            for (int j = 0; j < 8; j++) {
                float4 sp;
                sp.x = softplus(pf[j].x); sp.y = softplus(pf[j].y);
                sp.z = softplus(pf[j].z); sp.w = softplus(pf[j].w);
                ksacc += (sp.x + sp.y) + (sp.z + sp.w);
                split_store4(sp, hip + 4 * j, lop + 4 * j);
            }
        } else {
#pragma unroll
            for (int j = 0; j < 8; j++) split_store4(pf[j], hip + 4 * j, lop + 4 * j);
        }
        __syncthreads();
        if (s < 31) {
            const float4* np = (const float4*)(gp + (s + 1) * 32);
#pragma unroll
            for (int j = 0; j < 8; j++) pf[j] = np[j];
        }
        const __half* VH = tb,             *VL = tb + TILE_H;
        const __half* KH = tb + 2 * TILE_H, *KL = tb + 3 * TILE_H;
#pragma unroll
        for (int ks = 0; ks < 2; ks++) {
            wmma::fragment<wmma::matrix_a, 16, 16, 16, __half, wmma::row_major> ah[2], al[2];
            wmma::fragment<wmma::matrix_b, 16, 16, 16, __half, wmma::col_major> bhf[4], blf[4];
#pragma unroll
            for (int i = 0; i < 2; i++) {
                wmma::load_matrix_sync(ah[i], VH + (wm * 32 + i * 16) * LD1 + ks * 16, LD1);
                wmma::load_matrix_sync(al[i], VL + (wm * 32 + i * 16) * LD1 + ks * 16, LD1);
            }
#pragma unroll
            for (int j = 0; j < 4; j++) {
                wmma::load_matrix_sync(bhf[j], KH + (wn * 64 + j * 16) * LD1 + ks * 16, LD1);
                wmma::load_matrix_sync(blf[j], KL + (wn * 64 + j * 16) * LD1 + ks * 16, LD1);
            }
#pragma unroll
            for (int i = 0; i < 2; i++)
#pragma unroll
                for (int j = 0; j < 4; j++) {
                    wmma::mma_sync(acc[i][j], ah[i], bhf[j], acc[i][j]);   // hi*hi
                    wmma::mma_sync(acc[i][j], ah[i], blf[j], acc[i][j]);   // hi*lo
                    wmma::mma_sync(acc[i][j], al[i], bhf[j], acc[i][j]);   // lo*hi
                }
        }
    }

    if (isK) atomicAdd(&g_ksum[bh * CDIM + row], ksacc);

    __syncthreads();
    float* outp = (float*)smh;   // reuse tile smem: 128x128 fp32 = 64KB <= 80KB
#pragma unroll
    for (int i = 0; i < 2; i++)
#pragma unroll
        for (int j = 0; j < 4; j++)
            wmma::store_matrix_sync(outp + (wm * 32 + i * 16) * 128 + wn * 64 + j * 16,
                                    acc[i][j], 128, wmma::mem_row_major);
    __syncthreads();
    float* dst = g_kvt + (size_t)bh * CDIM * CDIM;
#pragma unroll
    for (int i = 0; i < 64; i++) {
        int idx = i * 256 + tid;
        atomicAdd(dst + idx, outp[idx]);
    }
}

// ==================== pass 2 ====================
// out[d,n] = SCALE * zinv[n] * sum_c kv_t[d][c] * softplus(q)[c,n]
// grid (128, BH): one 128-wide n tile per CTA; K = c = 128, 8 wmma k-steps.
#define LD2   136
#define A_HI  0
#define A_LO  (128 * LD2)
#define B_HI  (2 * 128 * LD2)
#define B_LO  (3 * 128 * LD2)
#define P2_TILE_H (4 * 128 * LD2)                      // 69632 halves = 139264 B
#define P2_SMEM (P2_TILE_H * 2 + (8 * 128 + 128 + 128) * 4)   // 144384 B

__global__ void __launch_bounds__(256, 1) pass2_kernel(const float* __restrict__ x,
                                                       float* __restrict__ out) {
    extern __shared__ __align__(16) __half smh[];
    float* zp   = (float*)(smh + P2_TILE_H);   // [8 warps][128 n]
    float* zinv = zp + 8 * 128;
    float* ksm  = zinv + 128;
    const int tid = threadIdx.x, wid = tid >> 5, lane = tid & 31;
    const int bh = blockIdx.y, b = bh >> 2, h = bh & 3;

    if (tid < 128) ksm[tid] = g_ksum[bh * CDIM + tid];
    __syncthreads();

    // Stage A = kv_t[d][c]: thread -> (d = tid>>1, 64-col half)
    {
        const int d = tid >> 1, cb = (tid & 1) * 64;
        const float* ap = g_kvt + (size_t)bh * CDIM * CDIM + d * CDIM + cb;
        __half* hip = smh + A_HI + d * LD2 + cb;
        __half* lop = smh + A_LO + d * LD2 + cb;
#pragma unroll
        for (int j = 0; j < 16; j++)
            split_store4(*(const float4*)(ap + 4 * j), hip + 4 * j, lop + 4 * j);
    }

    // Stage B = softplus(q)[c][n] + z partials (coalesced: 8 threads per c row)
    const size_t qbase = ((size_t)(b * CTOT + h * CDIM)) * N_POS + (size_t)blockIdx.x * 128;
    const float* qp = x + qbase;
    float zacc[16];
#pragma unroll
    for (int j = 0; j < 16; j++) zacc[j] = 0.0f;
    const int seg = tid & 7, nloc = seg * 16, clq = tid >> 3;
#pragma unroll
    for (int s = 0; s < 4; s++) {
        int c = s * 32 + clq;
        float kw = ksm[c];
        const float* qrow = qp + (size_t)c * N_POS + nloc;
        __half* hip = smh + B_HI + c * LD2 + nloc;
        __half* lop = smh + B_LO + c * LD2 + nloc;
#pragma unroll
        for (int j = 0; j < 4; j++) {
            float4 f = *(const float4*)(qrow + 4 * j);
            float4 sp;
            sp.x = softplus(f.x); sp.y = softplus(f.y);
            sp.z = softplus(f.z); sp.w = softplus(f.w);
            zacc[4 * j + 0] += sp.x * kw; zacc[4 * j + 1] += sp.y * kw;
            zacc[4 * j + 2] += sp.z * kw; zacc[4 * j + 3] += sp.w * kw;
            split_store4(sp, hip + 4 * j, lop + 4 * j);
        }
    }
    // reduce z over the warp's 4 c-rows (lanes xor 8, 16 share the same seg)
#pragma unroll
    for (int j = 0; j < 16; j++) {
        zacc[j] += __shfl_xor_sync(0xffffffffu, zacc[j], 8);
        zacc[j] += __shfl_xor_sync(0xffffffffu, zacc[j], 16);
    }
    if (lane < 8) {
#pragma unroll
        for (int j = 0; j < 16; j++) zp[wid * 128 + lane * 16 + j] = zacc[j];
    }
    __syncthreads();
    if (tid < 128) {
        float z = 0.0f;
#pragma unroll
        for (int w = 0; w < 8; w++) z += zp[w * 128 + tid];
        zinv[tid] = SCALE / (z * SCALE + (float)N_POS);
    }

    // Compute: warp tile m(d)=32*wm x n=64*wn, K = 8 steps of 16 c
    const int wm = wid & 3, wn = wid >> 2;
    wmma::fragment<wmma::accumulator, 16, 16, 16, float> acc[2][4];
#pragma unroll
    for (int i = 0; i < 2; i++)
#pragma unroll
        for (int j = 0; j < 4; j++) wmma::fill_fragment(acc[i][j], 0.0f);

    const __half* AHp = smh + A_HI, *ALp = smh + A_LO;
    const __half* BHp = smh + B_HI, *BLp = smh + B_LO;
#pragma unroll
    for (int ks = 0; ks < 8; ks++) {
        wmma::fragment<wmma::matrix_a, 16, 16, 16, __half, wmma::row_major> ah[2], al[2];
        wmma::fragment<wmma::matrix_b, 16, 16, 16, __half, wmma::row_major> bhf[4], blf[4];
#pragma unroll
        for (int i = 0; i < 2; i++) {
            wmma::load_matrix_sync(ah[i], AHp + (wm * 32 + i * 16) * LD2 + ks * 16, LD2);
            wmma::load_matrix_sync(al[i], ALp + (wm * 32 + i * 16) * LD2 + ks * 16, LD2);
        }
#pragma unroll
        for (int j = 0; j < 4; j++) {
            wmma::load_matrix_sync(bhf[j], BHp + (ks * 16) * LD2 + wn * 64 + j * 16, LD2);
            wmma::load_matrix_sync(blf[j], BLp + (ks * 16) * LD2 + wn * 64 + j * 16, LD2);
        }
#pragma unroll
        for (int i = 0; i < 2; i++)
#pragma unroll
            for (int j = 0; j < 4; j++) {
                wmma::mma_sync(acc[i][j], ah[i], bhf[j], acc[i][j]);
                wmma::mma_sync(acc[i][j], ah[i], blf[j], acc[i][j]);
                wmma::mma_sync(acc[i][j], al[i], bhf[j], acc[i][j]);
            }
    }

    __syncthreads();                 // tiles dead; also orders zinv writes
    float* outp = (float*)smh;       // 128x128 fp32 = 64KB (reuses A region)
#pragma unroll
    for (int i = 0; i < 2; i++)
#pragma unroll
        for (int j = 0; j < 4; j++)
            wmma::store_matrix_sync(outp + (wm * 32 + i * 16) * 128 + wn * 64 + j * 16,
                                    acc[i][j], 128, wmma::mem_row_major);
    __syncthreads();

    float* obase = out + qbase;
#pragma unroll
    for (int i = 0; i < 16; i++) {
        int lin = i * 1024 + tid * 4;
        int d = lin >> 7, n = lin & 127;
        float4 v = *(float4*)(outp + lin);
        v.x *= zinv[n];     v.y *= zinv[n + 1];
        v.z *= zinv[n + 2]; v.w *= zinv[n + 3];
        *(float4*)(obase + (size_t)d * N_POS + n) = v;
    }
}

// ==================== launch ====================
extern "C" void kernel_launch(void* const* d_in, const int* in_sizes, int n_in,
                              void* d_out, int out_size) {
    (void)in_sizes; (void)n_in; (void)out_size;
    const float* x = (const float*)d_in[0];
    float* out = (float*)d_out;

    cudaFuncSetAttribute(pass1_kernel, cudaFuncAttributeMaxDynamicSharedMemorySize, P1_SMEM);
    cudaFuncSetAttribute(pass2_kernel, cudaFuncAttributeMaxDynamicSharedMemorySize, P2_SMEM);

    zero_kernel<<<(BH * CDIM * CDIM + 255) / 256, 256>>>();
    pass1_kernel<<<dim3(16, BH), 256, P1_SMEM>>>(x);
    pass2_kernel<<<dim3(128, BH), 256, P2_SMEM>>>(x, out);
}